// round 8
// baseline (speedup 1.0000x reference)
#include <cuda_runtime.h>
#include <math.h>

// Problem constants
#define NU 50000
#define NI 50000
#define NN 100000          // NU + NI
#define DD 64
#define NNZ 3200000
#define NLAYERS 3
#define NB 4096
#define L2_REG 1e-5f

#define SCAN_CHUNK 1024
#define SCAN_NBLK ((NN + SCAN_CHUNK - 1) / SCAN_CHUNK)   // 98
#define STAT_READY (1 << 30)
#define LOSS_NBLK (NB / 8)                               // 512 blocks of 8 warps

// ---------------- device scratch (no allocs allowed) ----------------
__device__ __align__(256) float g_E0[NN * DD];
__device__ __align__(256) float g_E1[NN * DD];
__device__ __align__(256) unsigned int g_B0[NN * 32];   // bf16x2 shadow of E0
__device__ __align__(256) unsigned int g_B1[NN * 32];   // bf16x2 shadow of E1
__device__ __align__(256) float g_Lmul[NN * DD];
__device__ __align__(256) float g_alle[NN * DD * (NLAYERS + 1)];   // [N, 256]
__device__ int   g_deg[NN];          // zero-init; re-zeroed by scan each call
__device__ int   g_rowptr[NN + 1];
__device__ int   g_cursor[NN];
__device__ __align__(16) int2 g_edge[NNZ];   // (col, val bits)
__device__ int   g_stat[SCAN_NBLK];  // zero-init; reset in-kernel each call
__device__ int   g_bar;              // scan->scatter barrier (self-resetting)
__device__ int   g_bar2;
__device__ int   g_done;             // loss finalize counter (self-resetting)
__device__ float g_acc[4];           // bpr_sum, u^2, p^2, n^2 (finalize resets)

// ---------------- f32x2 helpers (FFMA2: PTX-only pattern) ----------------
typedef unsigned long long ull;

__device__ __forceinline__ ull fma2(ull a, ull b, ull c) {
    ull d;
    asm("fma.rn.f32x2 %0, %1, %2, %3;" : "=l"(d) : "l"(a), "l"(b), "l"(c));
    return d;
}
__device__ __forceinline__ ull pk2(float lo, float hi) {
    ull d;
    asm("mov.b64 %0, {%1, %2};" : "=l"(d) : "f"(lo), "f"(hi));
    return d;
}
__device__ __forceinline__ float2 upk(ull v) {
    float2 f;
    asm("mov.b64 {%0, %1}, %2;" : "=f"(f.x), "=f"(f.y) : "l"(v));
    return f;
}
__device__ __forceinline__ unsigned int bf2pack(float lo, float hi) {
    unsigned int r;
    asm("cvt.rn.bf16x2.f32 %0, %1, %2;" : "=r"(r) : "f"(hi), "f"(lo));
    return r;
}
// acc += bf16x2 widened to f32x2, times vv (both halves = edge weight)
__device__ __forceinline__ void bfma(ull& acc, unsigned int bits, ull vv) {
    unsigned int lo = bits << 16;
    unsigned int hi = bits & 0xffff0000u;
    ull pair;
    asm("mov.b64 %0, {%1, %2};" : "=l"(pair) : "r"(lo), "r"(hi));
    acc = fma2(pair, vv, acc);
}

// ---------------- 1: count + E init (fp32 + bf16 shadow) ----------------
__global__ void k_count_init(const int* __restrict__ rows,
                             const float* __restrict__ ue,
                             const float* __restrict__ ie) {
    int i = blockIdx.x * blockDim.x + threadIdx.x;
    if (i < NNZ) atomicAdd(&g_deg[rows[i]], 1);
    if (i < NN * (DD / 4)) {
        int n = i >> 4;
        int c = i & 15;
        const float4* src;
        int srow;
        if (n < NU) { src = (const float4*)ue; srow = n; }
        else        { src = (const float4*)ie; srow = n - NU; }
        float4 v = src[srow * 16 + c];
        ((float4*)g_E0)[i] = v;
        ((float4*)g_alle)[n * 64 + c] = v;
        uint2 b;
        b.x = bf2pack(v.x, v.y);
        b.y = bf2pack(v.z, v.w);
        ((uint2*)g_B0)[i] = b;
    }
}

// ---------------- 2: fused scan + scatter (98 co-resident blocks) ----------------
__global__ void k_scan_scatter(const int* __restrict__ rows,
                               const int* __restrict__ cols,
                               const float* __restrict__ vals) {
    __shared__ int s[SCAN_CHUNK];
    __shared__ int wsum[4];
    __shared__ int s_off;
    int b = blockIdx.x;
    int t = threadIdx.x;
    int i = b * SCAN_CHUNK + t;
    int v = (i < NN) ? g_deg[i] : 0;
    if (i < NN) g_deg[i] = 0;            // maintain zero invariant
    s[t] = v;
    __syncthreads();
    for (int off = 1; off < SCAN_CHUNK; off <<= 1) {
        int x = 0;
        if (t >= off) x = s[t - off];
        __syncthreads();
        s[t] += x;
        __syncthreads();
    }
    if (t == SCAN_CHUNK - 1) atomicExch(&g_stat[b], s[t] | STAT_READY);
    int part = 0;
    if (t < b) {
        int st;
        do { st = atomicAdd(&g_stat[t], 0); } while (!(st & STAT_READY));
        part = st & (STAT_READY - 1);
    }
    #pragma unroll
    for (int off = 16; off > 0; off >>= 1)
        part += __shfl_xor_sync(0xffffffffu, part, off);
    if ((t & 31) == 0 && (t >> 5) < 4) wsum[t >> 5] = part;
    __syncthreads();
    if (t == 0) s_off = wsum[0] + wsum[1] + wsum[2] + wsum[3];
    __syncthreads();
    int off = s_off;
    if (i < NN) {
        int incl = s[t] + off;
        g_rowptr[1 + i] = incl;
        g_cursor[i] = incl - v;
    }
    if (b == 0 && t == 0) g_rowptr[0] = 0;

    // ---- grid barrier (all 98 blocks co-resident) ----
    __threadfence();
    __syncthreads();
    if (t == 0) {
        atomicAdd(&g_bar, 1);
        while (atomicAdd(&g_bar, 0) < SCAN_NBLK) { }
        g_stat[b] = 0;                          // safe: all lookbacks done
        int r2 = atomicAdd(&g_bar2, 1);
        if (r2 == SCAN_NBLK - 1) { g_bar = 0; g_bar2 = 0; }   // last resets
    }
    __syncthreads();

    // ---- scatter: grid-stride over edges ----
    for (int e = b * SCAN_CHUNK + t; e < NNZ; e += SCAN_NBLK * SCAN_CHUNK) {
        int r = rows[e];
        int p = atomicAdd(&g_cursor[r], 1);
        int2 pr;
        pr.x = cols[e];
        pr.y = __float_as_int(vals[e]);
        g_edge[p] = pr;
    }
}

// ---------------- 3: SpMM — warp/node, bf16 rows, 4 edges per LDG.128 ----------
__global__ void __launch_bounds__(256) k_spmm(int cur) {
    const uint4* __restrict__ B4 = (const uint4*)(cur ? g_B1 : g_B0);
    __shared__ int2 sedge[8][32];
    int warp = (blockIdx.x * blockDim.x + threadIdx.x) >> 5;
    int wid  = threadIdx.x >> 5;
    int lane = threadIdx.x & 31;
    int g    = lane >> 3;         // edge slot within group of 4
    int sub  = lane & 7;          // uint4 slot within the 128B bf16 row
    if (warp >= NN) return;
    int start = g_rowptr[warp];
    int end   = g_rowptr[warp + 1];
    ull a0 = 0, a1 = 0, a2 = 0, a3 = 0;   // dims sub*8 + {0,1},{2,3},{4,5},{6,7}
    int e0 = start;
    for (; e0 + 32 <= end; e0 += 32) {
        sedge[wid][lane] = g_edge[e0 + lane];
        __syncwarp();
        #pragma unroll
        for (int i0 = 0; i0 < 8; i0 += 4) {
            int2 eA = sedge[wid][4 * (i0 + 0) + g];
            int2 eB = sedge[wid][4 * (i0 + 1) + g];
            int2 eC = sedge[wid][4 * (i0 + 2) + g];
            int2 eD = sedge[wid][4 * (i0 + 3) + g];
            uint4 qA = B4[eA.x * 8 + sub];
            uint4 qB = B4[eB.x * 8 + sub];
            uint4 qC = B4[eC.x * 8 + sub];
            uint4 qD = B4[eD.x * 8 + sub];
            ull vA = pk2(__int_as_float(eA.y), __int_as_float(eA.y));
            ull vB = pk2(__int_as_float(eB.y), __int_as_float(eB.y));
            ull vC = pk2(__int_as_float(eC.y), __int_as_float(eC.y));
            ull vD = pk2(__int_as_float(eD.y), __int_as_float(eD.y));
            bfma(a0, qA.x, vA); bfma(a1, qA.y, vA); bfma(a2, qA.z, vA); bfma(a3, qA.w, vA);
            bfma(a0, qB.x, vB); bfma(a1, qB.y, vB); bfma(a2, qB.z, vB); bfma(a3, qB.w, vB);
            bfma(a0, qC.x, vC); bfma(a1, qC.y, vC); bfma(a2, qC.z, vC); bfma(a3, qC.w, vC);
            bfma(a0, qD.x, vD); bfma(a1, qD.y, vD); bfma(a2, qD.z, vD); bfma(a3, qD.w, vD);
        }
        __syncwarp();
    }
    int rem = end - e0;
    if (rem > 0) {
        sedge[wid][lane] = (lane < rem) ? g_edge[e0 + lane] : make_int2(0, 0);
        __syncwarp();
        int ngrp = (rem + 3) >> 2;
        for (int i = 0; i < ngrp; i++) {
            int2 ed = sedge[wid][4 * i + g];
            uint4 q = B4[ed.x * 8 + sub];
            ull vv = pk2(__int_as_float(ed.y), __int_as_float(ed.y));
            bfma(a0, q.x, vv); bfma(a1, q.y, vv); bfma(a2, q.z, vv); bfma(a3, q.w, vv);
        }
    }
    // reduce across the 4 edge-groups (lane bits 3,4)
    float2 f0 = upk(a0), f1 = upk(a1), f2 = upk(a2), f3 = upk(a3);
    #pragma unroll
    for (int off = 8; off <= 16; off <<= 1) {
        f0.x += __shfl_xor_sync(0xffffffffu, f0.x, off);
        f0.y += __shfl_xor_sync(0xffffffffu, f0.y, off);
        f1.x += __shfl_xor_sync(0xffffffffu, f1.x, off);
        f1.y += __shfl_xor_sync(0xffffffffu, f1.y, off);
        f2.x += __shfl_xor_sync(0xffffffffu, f2.x, off);
        f2.y += __shfl_xor_sync(0xffffffffu, f2.y, off);
        f3.x += __shfl_xor_sync(0xffffffffu, f3.x, off);
        f3.y += __shfl_xor_sync(0xffffffffu, f3.y, off);
    }
    if (lane < 8) {
        *(float4*)&g_Lmul[warp * DD + lane * 8]     = make_float4(f0.x, f0.y, f1.x, f1.y);
        *(float4*)&g_Lmul[warp * DD + lane * 8 + 4] = make_float4(f2.x, f2.y, f3.x, f3.y);
    }
}

// ---------------- 4: fused GEMM — 64 rows/block, 3 blocks/SM ----------------
// 256 threads: tx = tid&15 -> cols j0=tx*4; ty = tid>>4 -> rows r0=ty*4.
// A/R transposed tiles [64 k][68], one LDS.128 per operand per k covers all
// 4 rows; weights LDS.128 per matrix. 16 FFMA2 per thread per k.
#define TS2 68
#define GEMM_SMEM_FLOATS (2 * 64 * TS2 + 2 * 64 * 64)

__global__ void __launch_bounds__(256, 3) k_gemm(int cur, int l,
                                                 const float* __restrict__ W1,
                                                 const float* __restrict__ b1,
                                                 const float* __restrict__ W2,
                                                 const float* __restrict__ b2) {
    extern __shared__ float smem[];
    float* AsT = smem;                 // [64][68]
    float* RsT = AsT + 64 * TS2;       // [64][68]
    float* W1s = RsT + 64 * TS2;       // [64][64]
    float* W2s = W1s + 64 * 64;        // [64][64]

    const float*  Ecur  = cur ? g_E1 : g_E0;
    float*        Enext = cur ? g_E0 : g_E1;
    unsigned int* Bnext = cur ? g_B0 : g_B1;

    int tid  = threadIdx.x;
    int lane = tid & 31;
    int wid  = tid >> 5;
    int tx = tid & 15;
    int ty = tid >> 4;
    int j0 = tx * 4;
    int r0 = ty * 4;
    int n0 = blockIdx.x * 64;
    int lw = l * 64 * 64;
    int lb = l * 64;

    for (int i = tid; i < 4096; i += 256) {
        W1s[i] = W1[lw + i];
        W2s[i] = W2[lw + i];
    }

    // staging: warp per row (8 rows round-robin); lane covers k=lane, k=lane+32
    for (int row = wid; row < 64; row += 8) {
        int n = n0 + row;
        float lmA = 0.0f, lmB = 0.0f, evA = 0.0f, evB = 0.0f;
        if (n < NN) {
            lmA = g_Lmul[n * DD + lane];
            lmB = g_Lmul[n * DD + lane + 32];
            evA = Ecur[n * DD + lane];
            evB = Ecur[n * DD + lane + 32];
        }
        AsT[lane * TS2 + row]        = lmA + evA;
        AsT[(lane + 32) * TS2 + row] = lmB + evB;
        RsT[lane * TS2 + row]        = lmA * evA;
        RsT[(lane + 32) * TS2 + row] = lmB * evB;
    }
    __syncthreads();

    // acc[p][j]: rows (r0+2p, r0+2p+1) packed f32x2, col j0+j
    ull acc[2][4];
    #pragma unroll
    for (int j = 0; j < 4; j++) {
        float b = b1[lb + j0 + j] + b2[lb + j0 + j];
        ull bb = pk2(b, b);
        acc[0][j] = bb;
        acc[1][j] = bb;
    }

    #pragma unroll 8
    for (int k = 0; k < 64; k++) {
        ulonglong2 A = *(const ulonglong2*)&AsT[k * TS2 + r0];  // rows r0..r0+3
        ulonglong2 R = *(const ulonglong2*)&RsT[k * TS2 + r0];
        float4 w1 = *(const float4*)&W1s[k * 64 + j0];
        float4 w2 = *(const float4*)&W2s[k * 64 + j0];
        ull w1d[4] = { pk2(w1.x, w1.x), pk2(w1.y, w1.y), pk2(w1.z, w1.z), pk2(w1.w, w1.w) };
        ull w2d[4] = { pk2(w2.x, w2.x), pk2(w2.y, w2.y), pk2(w2.z, w2.z), pk2(w2.w, w2.w) };
        #pragma unroll
        for (int j = 0; j < 4; j++) {
            acc[0][j] = fma2(A.x, w1d[j], acc[0][j]);
            acc[0][j] = fma2(R.x, w2d[j], acc[0][j]);
            acc[1][j] = fma2(A.y, w1d[j], acc[1][j]);
            acc[1][j] = fma2(R.y, w2d[j], acc[1][j]);
        }
    }

    // leaky relu + per-row squared sums (4 rows/thread)
    float vals_[4][4];
    float sq[4];
    #pragma unroll
    for (int p = 0; p < 2; p++) {
        float sx = 0.0f, sy = 0.0f;
        #pragma unroll
        for (int j = 0; j < 4; j++) {
            float2 v = upk(acc[p][j]);
            v.x = (v.x >= 0.0f) ? v.x : 0.2f * v.x;
            v.y = (v.y >= 0.0f) ? v.y : 0.2f * v.y;
            vals_[2 * p][j]     = v.x;
            vals_[2 * p + 1][j] = v.y;
            sx = fmaf(v.x, v.x, sx);
            sy = fmaf(v.y, v.y, sy);
        }
        sq[2 * p]     = sx;
        sq[2 * p + 1] = sy;
    }
    // reduce row norms across the 16 tx-lanes (xor <= 8 stays within ty group)
    #pragma unroll
    for (int i = 0; i < 4; i++) {
        #pragma unroll
        for (int off = 1; off <= 8; off <<= 1)
            sq[i] += __shfl_xor_sync(0xffffffffu, sq[i], off);
    }

    int colblk = (l + 1) * 64;
    #pragma unroll
    for (int i = 0; i < 4; i++) {
        int n = n0 + r0 + i;
        if (n < NN) {
            float inv = 1.0f / fmaxf(sqrtf(sq[i]), 1e-12f);
            float4 v = make_float4(vals_[i][0], vals_[i][1], vals_[i][2], vals_[i][3]);
            *(float4*)&Enext[n * DD + j0] = v;
            uint2 bv;
            bv.x = bf2pack(v.x, v.y);
            bv.y = bf2pack(v.z, v.w);
            *(uint2*)&Bnext[n * 32 + j0 / 2] = bv;
            float4 vn = make_float4(v.x * inv, v.y * inv, v.z * inv, v.w * inv);
            *(float4*)&g_alle[n * 256 + colblk + j0] = vn;
        }
    }
}

// ---------------- 5: loss + fused finalize ----------------
__global__ void k_loss(const int* __restrict__ users,
                       const int* __restrict__ pos,
                       const int* __restrict__ neg,
                       float* __restrict__ out) {
    int warp = (blockIdx.x * blockDim.x + threadIdx.x) >> 5;
    int lane = threadIdx.x & 31;
    if (warp < NB) {
        int uu = users[warp];
        int pp = pos[warp];
        int nn = neg[warp];
        const float4* A4 = (const float4*)g_alle;
        float pd = 0, nd = 0, su = 0, sp = 0, sn = 0;
        #pragma unroll
        for (int t = 0; t < 2; t++) {
            float4 u = A4[uu * 64 + lane * 2 + t];
            float4 p = A4[pp * 64 + lane * 2 + t];
            float4 q = A4[nn * 64 + lane * 2 + t];
            pd += u.x * p.x + u.y * p.y + u.z * p.z + u.w * p.w;
            nd += u.x * q.x + u.y * q.y + u.z * q.z + u.w * q.w;
            su += u.x * u.x + u.y * u.y + u.z * u.z + u.w * u.w;
            sp += p.x * p.x + p.y * p.y + p.z * p.z + p.w * p.w;
            sn += q.x * q.x + q.y * q.y + q.z * q.z + q.w * q.w;
        }
        #pragma unroll
        for (int off = 16; off > 0; off >>= 1) {
            pd += __shfl_xor_sync(0xffffffffu, pd, off);
            nd += __shfl_xor_sync(0xffffffffu, nd, off);
            su += __shfl_xor_sync(0xffffffffu, su, off);
            sp += __shfl_xor_sync(0xffffffffu, sp, off);
            sn += __shfl_xor_sync(0xffffffffu, sn, off);
        }
        if (lane == 0) {
            float d = pd - nd;
            float ls = fminf(d, 0.0f) - log1pf(expf(-fabsf(d)));
            atomicAdd(&g_acc[0], ls);
            atomicAdd(&g_acc[1], su);
            atomicAdd(&g_acc[2], sp);
            atomicAdd(&g_acc[3], sn);
        }
    }
    // last-block finalize
    __threadfence();
    __syncthreads();
    if (threadIdx.x == 0) {
        int r = atomicAdd(&g_done, 1);
        if (r == LOSS_NBLK - 1) {
            float a0 = atomicAdd(&g_acc[0], 0.0f);
            float a1 = atomicAdd(&g_acc[1], 0.0f);
            float a2 = atomicAdd(&g_acc[2], 0.0f);
            float a3 = atomicAdd(&g_acc[3], 0.0f);
            float bpr = -a0 / (float)NB;
            float l2norm = (a1 + a2 + sqrtf(a3)) * 0.5f;
            out[0] = bpr + L2_REG * l2norm / (float)NB;
            g_acc[0] = 0.0f; g_acc[1] = 0.0f; g_acc[2] = 0.0f; g_acc[3] = 0.0f;
            g_done = 0;
        }
    }
}

// ---------------- launch ----------------
extern "C" void kernel_launch(void* const* d_in, const int* in_sizes, int n_in,
                              void* d_out, int out_size) {
    const int*   users = (const int*)d_in[0];
    const int*   pos   = (const int*)d_in[1];
    const int*   neg   = (const int*)d_in[2];
    const int*   rows  = (const int*)d_in[3];
    const int*   cols  = (const int*)d_in[4];
    const float* vals  = (const float*)d_in[5];
    const float* ue    = (const float*)d_in[6];
    const float* ie    = (const float*)d_in[7];
    const float* W1    = (const float*)d_in[8];
    const float* b1    = (const float*)d_in[9];
    const float* W2    = (const float*)d_in[10];
    const float* b2    = (const float*)d_in[11];
    float* out = (float*)d_out;

    cudaFuncSetAttribute(k_gemm, cudaFuncAttributeMaxDynamicSharedMemorySize,
                         GEMM_SMEM_FLOATS * sizeof(float));

    // 1: count + E init (fp32 + bf16 shadow)
    k_count_init<<<(NNZ + 255) / 256, 256>>>(rows, ue, ie);
    // 2: fused scan + scatter (in-kernel grid barrier)
    k_scan_scatter<<<SCAN_NBLK, SCAN_CHUNK>>>(rows, cols, vals);

    // layers (launch idx 5 = k_gemm L1 -> ncu capture slot)
    int cur = 0;
    for (int l = 0; l < NLAYERS; l++) {
        k_spmm<<<(NN + 7) / 8, 256>>>(cur);
        k_gemm<<<(NN + 63) / 64, 256, GEMM_SMEM_FLOATS * sizeof(float)>>>(
            cur, l, W1, b1, W2, b2);
        cur ^= 1;
    }

    // loss + fused finalize
    k_loss<<<LOSS_NBLK, 256>>>(users, pos, neg, out);
}

// round 9
// speedup vs baseline: 1.0952x; 1.0952x over previous
#include <cuda_runtime.h>
#include <math.h>

// Problem constants
#define NU 50000
#define NI 50000
#define NN 100000          // NU + NI
#define DD 64
#define NNZ 3200000
#define NLAYERS 3
#define NB 4096
#define L2_REG 1e-5f

#define SCAN_CHUNK 1024
#define SCAN_NBLK ((NN + SCAN_CHUNK - 1) / SCAN_CHUNK)   // 98
#define STAT_READY (1 << 30)
#define LOSS_NBLK (NB / 8)                               // 512 blocks of 8 warps

// ---------------- device scratch (no allocs allowed) ----------------
__device__ __align__(256) float g_E0[NN * DD];
__device__ __align__(256) float g_E1[NN * DD];
__device__ __align__(256) unsigned int g_B0[NN * 32];   // bf16x2 shadow of E0
__device__ __align__(256) unsigned int g_B1[NN * 32];   // bf16x2 shadow of E1
__device__ __align__(256) float g_Lmul[NN * DD];
__device__ __align__(256) float g_alle[NN * DD * (NLAYERS + 1)];   // [N, 256]
__device__ int   g_deg[NN];          // zero-init; re-zeroed by scan each call
__device__ int   g_rowptr[NN + 1];
__device__ int   g_cursor[NN];
__device__ __align__(16) int2 g_edge[NNZ];   // (col, val bits)
__device__ int   g_stat[SCAN_NBLK];  // zero-init; reset in-kernel each call
__device__ int   g_bar;              // scan->scatter barrier (self-resetting)
__device__ int   g_bar2;
__device__ int   g_done;             // loss finalize counter (self-resetting)
__device__ float g_acc[4];           // bpr_sum, u^2, p^2, n^2 (finalize resets)

// ---------------- f32x2 helpers (FFMA2: PTX-only pattern) ----------------
typedef unsigned long long ull;

__device__ __forceinline__ ull fma2(ull a, ull b, ull c) {
    ull d;
    asm("fma.rn.f32x2 %0, %1, %2, %3;" : "=l"(d) : "l"(a), "l"(b), "l"(c));
    return d;
}
__device__ __forceinline__ ull pk2(float lo, float hi) {
    ull d;
    asm("mov.b64 %0, {%1, %2};" : "=l"(d) : "f"(lo), "f"(hi));
    return d;
}
__device__ __forceinline__ float2 upk(ull v) {
    float2 f;
    asm("mov.b64 {%0, %1}, %2;" : "=f"(f.x), "=f"(f.y) : "l"(v));
    return f;
}
__device__ __forceinline__ unsigned int bf2pack(float lo, float hi) {
    unsigned int r;
    asm("cvt.rn.bf16x2.f32 %0, %1, %2;" : "=r"(r) : "f"(hi), "f"(lo));
    return r;
}
// acc += bf16x2 widened to f32x2, times vv (both halves = edge weight)
__device__ __forceinline__ void bfma(ull& acc, unsigned int bits, ull vv) {
    unsigned int lo = bits << 16;
    unsigned int hi = bits & 0xffff0000u;
    ull pair;
    asm("mov.b64 %0, {%1, %2};" : "=l"(pair) : "r"(lo), "r"(hi));
    acc = fma2(pair, vv, acc);
}

// ---------------- 1: count + E init (fp32 + bf16 shadow) ----------------
__global__ void k_count_init(const int* __restrict__ rows,
                             const float* __restrict__ ue,
                             const float* __restrict__ ie) {
    int i = blockIdx.x * blockDim.x + threadIdx.x;
    if (i < NNZ) atomicAdd(&g_deg[rows[i]], 1);
    if (i < NN * (DD / 4)) {
        int n = i >> 4;
        int c = i & 15;
        const float4* src;
        int srow;
        if (n < NU) { src = (const float4*)ue; srow = n; }
        else        { src = (const float4*)ie; srow = n - NU; }
        float4 v = src[srow * 16 + c];
        ((float4*)g_E0)[i] = v;
        ((float4*)g_alle)[n * 64 + c] = v;
        uint2 b;
        b.x = bf2pack(v.x, v.y);
        b.y = bf2pack(v.z, v.w);
        ((uint2*)g_B0)[i] = b;
    }
}

// ---------------- 2: fused scan + scatter (98 co-resident blocks) ----------------
__global__ void k_scan_scatter(const int* __restrict__ rows,
                               const int* __restrict__ cols,
                               const float* __restrict__ vals) {
    __shared__ int s[SCAN_CHUNK];
    __shared__ int wsum[4];
    __shared__ int s_off;
    int b = blockIdx.x;
    int t = threadIdx.x;
    int i = b * SCAN_CHUNK + t;
    int v = (i < NN) ? g_deg[i] : 0;
    if (i < NN) g_deg[i] = 0;            // maintain zero invariant
    s[t] = v;
    __syncthreads();
    for (int off = 1; off < SCAN_CHUNK; off <<= 1) {
        int x = 0;
        if (t >= off) x = s[t - off];
        __syncthreads();
        s[t] += x;
        __syncthreads();
    }
    if (t == SCAN_CHUNK - 1) atomicExch(&g_stat[b], s[t] | STAT_READY);
    int part = 0;
    if (t < b) {
        int st;
        do { st = atomicAdd(&g_stat[t], 0); } while (!(st & STAT_READY));
        part = st & (STAT_READY - 1);
    }
    #pragma unroll
    for (int off = 16; off > 0; off >>= 1)
        part += __shfl_xor_sync(0xffffffffu, part, off);
    if ((t & 31) == 0 && (t >> 5) < 4) wsum[t >> 5] = part;
    __syncthreads();
    if (t == 0) s_off = wsum[0] + wsum[1] + wsum[2] + wsum[3];
    __syncthreads();
    int off = s_off;
    if (i < NN) {
        int incl = s[t] + off;
        g_rowptr[1 + i] = incl;
        g_cursor[i] = incl - v;
    }
    if (b == 0 && t == 0) g_rowptr[0] = 0;

    // ---- grid barrier (all 98 blocks co-resident) ----
    __threadfence();
    __syncthreads();
    if (t == 0) {
        atomicAdd(&g_bar, 1);
        while (atomicAdd(&g_bar, 0) < SCAN_NBLK) { }
        g_stat[b] = 0;                          // safe: all lookbacks done
        int r2 = atomicAdd(&g_bar2, 1);
        if (r2 == SCAN_NBLK - 1) { g_bar = 0; g_bar2 = 0; }   // last resets
    }
    __syncthreads();

    // ---- scatter: grid-stride over edges ----
    for (int e = b * SCAN_CHUNK + t; e < NNZ; e += SCAN_NBLK * SCAN_CHUNK) {
        int r = rows[e];
        int p = atomicAdd(&g_cursor[r], 1);
        int2 pr;
        pr.x = cols[e];
        pr.y = __float_as_int(vals[e]);
        g_edge[p] = pr;
    }
}

// ---------------- 3: SpMM — warp/node, bf16 rows, 4 edges per LDG.128 ----------
__global__ void __launch_bounds__(256) k_spmm(int cur) {
    const uint4* __restrict__ B4 = (const uint4*)(cur ? g_B1 : g_B0);
    __shared__ int2 sedge[8][32];
    int warp = (blockIdx.x * blockDim.x + threadIdx.x) >> 5;
    int wid  = threadIdx.x >> 5;
    int lane = threadIdx.x & 31;
    int g    = lane >> 3;         // edge slot within group of 4
    int sub  = lane & 7;          // uint4 slot within the 128B bf16 row
    if (warp >= NN) return;
    int start = g_rowptr[warp];
    int end   = g_rowptr[warp + 1];
    ull a0 = 0, a1 = 0, a2 = 0, a3 = 0;   // dims sub*8 + {0,1},{2,3},{4,5},{6,7}
    int e0 = start;
    for (; e0 + 32 <= end; e0 += 32) {
        sedge[wid][lane] = g_edge[e0 + lane];
        __syncwarp();
        #pragma unroll
        for (int i0 = 0; i0 < 8; i0 += 4) {
            int2 eA = sedge[wid][4 * (i0 + 0) + g];
            int2 eB = sedge[wid][4 * (i0 + 1) + g];
            int2 eC = sedge[wid][4 * (i0 + 2) + g];
            int2 eD = sedge[wid][4 * (i0 + 3) + g];
            uint4 qA = B4[eA.x * 8 + sub];
            uint4 qB = B4[eB.x * 8 + sub];
            uint4 qC = B4[eC.x * 8 + sub];
            uint4 qD = B4[eD.x * 8 + sub];
            ull vA = pk2(__int_as_float(eA.y), __int_as_float(eA.y));
            ull vB = pk2(__int_as_float(eB.y), __int_as_float(eB.y));
            ull vC = pk2(__int_as_float(eC.y), __int_as_float(eC.y));
            ull vD = pk2(__int_as_float(eD.y), __int_as_float(eD.y));
            bfma(a0, qA.x, vA); bfma(a1, qA.y, vA); bfma(a2, qA.z, vA); bfma(a3, qA.w, vA);
            bfma(a0, qB.x, vB); bfma(a1, qB.y, vB); bfma(a2, qB.z, vB); bfma(a3, qB.w, vB);
            bfma(a0, qC.x, vC); bfma(a1, qC.y, vC); bfma(a2, qC.z, vC); bfma(a3, qC.w, vC);
            bfma(a0, qD.x, vD); bfma(a1, qD.y, vD); bfma(a2, qD.z, vD); bfma(a3, qD.w, vD);
        }
        __syncwarp();
    }
    int rem = end - e0;
    if (rem > 0) {
        sedge[wid][lane] = (lane < rem) ? g_edge[e0 + lane] : make_int2(0, 0);
        __syncwarp();
        int ngrp = (rem + 3) >> 2;
        for (int i = 0; i < ngrp; i++) {
            int2 ed = sedge[wid][4 * i + g];
            uint4 q = B4[ed.x * 8 + sub];
            ull vv = pk2(__int_as_float(ed.y), __int_as_float(ed.y));
            bfma(a0, q.x, vv); bfma(a1, q.y, vv); bfma(a2, q.z, vv); bfma(a3, q.w, vv);
        }
    }
    // reduce across the 4 edge-groups (lane bits 3,4)
    float2 f0 = upk(a0), f1 = upk(a1), f2 = upk(a2), f3 = upk(a3);
    #pragma unroll
    for (int off = 8; off <= 16; off <<= 1) {
        f0.x += __shfl_xor_sync(0xffffffffu, f0.x, off);
        f0.y += __shfl_xor_sync(0xffffffffu, f0.y, off);
        f1.x += __shfl_xor_sync(0xffffffffu, f1.x, off);
        f1.y += __shfl_xor_sync(0xffffffffu, f1.y, off);
        f2.x += __shfl_xor_sync(0xffffffffu, f2.x, off);
        f2.y += __shfl_xor_sync(0xffffffffu, f2.y, off);
        f3.x += __shfl_xor_sync(0xffffffffu, f3.x, off);
        f3.y += __shfl_xor_sync(0xffffffffu, f3.y, off);
    }
    if (lane < 8) {
        *(float4*)&g_Lmul[warp * DD + lane * 8]     = make_float4(f0.x, f0.y, f1.x, f1.y);
        *(float4*)&g_Lmul[warp * DD + lane * 8 + 4] = make_float4(f2.x, f2.y, f3.x, f3.y);
    }
}

// ---------------- 4: fused GEMM — 128 rows/block, 128 threads, 8x8/thread ------
// tx = tid&7 -> cols j0=tx*8; ty = tid>>3 -> rows r0=ty*8.
// Per thread per k: 2 LDS.128 A + 2 R + 2 w1 + 2 w2 = 128B for 128 FMA (1 B/FMA).
#define TS3 132
#define GEMM_SMEM_FLOATS (2 * 64 * TS3 + 2 * 64 * 64)

__global__ void __launch_bounds__(128, 2) k_gemm(int cur, int l,
                                                 const float* __restrict__ W1,
                                                 const float* __restrict__ b1,
                                                 const float* __restrict__ W2,
                                                 const float* __restrict__ b2) {
    extern __shared__ float smem[];
    float* AsT = smem;                 // [64][132]  (k-major, row minor)
    float* RsT = AsT + 64 * TS3;       // [64][132]
    float* W1s = RsT + 64 * TS3;       // [64][64]
    float* W2s = W1s + 64 * 64;        // [64][64]

    const float*  Ecur  = cur ? g_E1 : g_E0;
    float*        Enext = cur ? g_E0 : g_E1;
    unsigned int* Bnext = cur ? g_B0 : g_B1;

    int tid = threadIdx.x;
    int tx = tid & 7;
    int ty = tid >> 3;
    int j0 = tx * 8;
    int r0 = ty * 8;
    int n0 = blockIdx.x * 128;
    int lw = l * 64 * 64;
    int lb = l * 64;

    // load weights (1024 float4 per matrix; 8 per thread)
    {
        const float4* w1g = (const float4*)(W1 + lw);
        const float4* w2g = (const float4*)(W2 + lw);
        float4* w1s = (float4*)W1s;
        float4* w2s = (float4*)W2s;
        #pragma unroll
        for (int i = 0; i < 8; i++) {
            w1s[tid + 128 * i] = w1g[tid + 128 * i];
            w2s[tid + 128 * i] = w2g[tid + 128 * i];
        }
    }

    // staging: thread per row (row = tid), 16 float4 per array
    {
        int n = n0 + tid;
        const float4* LM4 = (const float4*)g_Lmul;
        const float4* EC4 = (const float4*)Ecur;
        #pragma unroll 4
        for (int c = 0; c < 16; c++) {
            float4 lm = make_float4(0, 0, 0, 0), ev = make_float4(0, 0, 0, 0);
            if (n < NN) {
                lm = LM4[n * 16 + c];
                ev = EC4[n * 16 + c];
            }
            int k = c * 4;
            AsT[(k + 0) * TS3 + tid] = lm.x + ev.x;
            AsT[(k + 1) * TS3 + tid] = lm.y + ev.y;
            AsT[(k + 2) * TS3 + tid] = lm.z + ev.z;
            AsT[(k + 3) * TS3 + tid] = lm.w + ev.w;
            RsT[(k + 0) * TS3 + tid] = lm.x * ev.x;
            RsT[(k + 1) * TS3 + tid] = lm.y * ev.y;
            RsT[(k + 2) * TS3 + tid] = lm.z * ev.z;
            RsT[(k + 3) * TS3 + tid] = lm.w * ev.w;
        }
    }
    __syncthreads();

    // acc[p][j]: rows (r0+2p, r0+2p+1) packed f32x2, col j0+j  (4x8 = 32 ull)
    ull acc[4][8];
    #pragma unroll
    for (int j = 0; j < 8; j++) {
        float b = b1[lb + j0 + j] + b2[lb + j0 + j];
        ull bb = pk2(b, b);
        #pragma unroll
        for (int p = 0; p < 4; p++) acc[p][j] = bb;
    }

    #pragma unroll 4
    for (int k = 0; k < 64; k++) {
        ulonglong2 A03 = *(const ulonglong2*)&AsT[k * TS3 + r0];      // rows r0..r0+3
        ulonglong2 A47 = *(const ulonglong2*)&AsT[k * TS3 + r0 + 4];  // rows r0+4..r0+7
        ulonglong2 R03 = *(const ulonglong2*)&RsT[k * TS3 + r0];
        ulonglong2 R47 = *(const ulonglong2*)&RsT[k * TS3 + r0 + 4];
        float4 w1a = *(const float4*)&W1s[k * 64 + j0];
        float4 w1b = *(const float4*)&W1s[k * 64 + j0 + 4];
        float4 w2a = *(const float4*)&W2s[k * 64 + j0];
        float4 w2b = *(const float4*)&W2s[k * 64 + j0 + 4];
        ull w1d[8] = { pk2(w1a.x, w1a.x), pk2(w1a.y, w1a.y), pk2(w1a.z, w1a.z), pk2(w1a.w, w1a.w),
                       pk2(w1b.x, w1b.x), pk2(w1b.y, w1b.y), pk2(w1b.z, w1b.z), pk2(w1b.w, w1b.w) };
        ull w2d[8] = { pk2(w2a.x, w2a.x), pk2(w2a.y, w2a.y), pk2(w2a.z, w2a.z), pk2(w2a.w, w2a.w),
                       pk2(w2b.x, w2b.x), pk2(w2b.y, w2b.y), pk2(w2b.z, w2b.z), pk2(w2b.w, w2b.w) };
        #pragma unroll
        for (int j = 0; j < 8; j++) {
            acc[0][j] = fma2(A03.x, w1d[j], acc[0][j]);
            acc[0][j] = fma2(R03.x, w2d[j], acc[0][j]);
            acc[1][j] = fma2(A03.y, w1d[j], acc[1][j]);
            acc[1][j] = fma2(R03.y, w2d[j], acc[1][j]);
            acc[2][j] = fma2(A47.x, w1d[j], acc[2][j]);
            acc[2][j] = fma2(R47.x, w2d[j], acc[2][j]);
            acc[3][j] = fma2(A47.y, w1d[j], acc[3][j]);
            acc[3][j] = fma2(R47.y, w2d[j], acc[3][j]);
        }
    }

    // leaky relu + per-row squared sums (8 rows/thread, 8 cols each)
    float vals_[8][8];
    float sq[8];
    #pragma unroll
    for (int p = 0; p < 4; p++) {
        float sx = 0.0f, sy = 0.0f;
        #pragma unroll
        for (int j = 0; j < 8; j++) {
            float2 v = upk(acc[p][j]);
            v.x = (v.x >= 0.0f) ? v.x : 0.2f * v.x;
            v.y = (v.y >= 0.0f) ? v.y : 0.2f * v.y;
            vals_[2 * p][j]     = v.x;
            vals_[2 * p + 1][j] = v.y;
            sx = fmaf(v.x, v.x, sx);
            sy = fmaf(v.y, v.y, sy);
        }
        sq[2 * p]     = sx;
        sq[2 * p + 1] = sy;
    }
    // reduce row norms across the 8 tx-lanes (xor <= 4 stays within ty group)
    #pragma unroll
    for (int i = 0; i < 8; i++) {
        #pragma unroll
        for (int off = 1; off <= 4; off <<= 1)
            sq[i] += __shfl_xor_sync(0xffffffffu, sq[i], off);
    }

    int colblk = (l + 1) * 64;
    #pragma unroll
    for (int i = 0; i < 8; i++) {
        int n = n0 + r0 + i;
        if (n < NN) {
            float inv = 1.0f / fmaxf(sqrtf(sq[i]), 1e-12f);
            float4 va = make_float4(vals_[i][0], vals_[i][1], vals_[i][2], vals_[i][3]);
            float4 vb = make_float4(vals_[i][4], vals_[i][5], vals_[i][6], vals_[i][7]);
            *(float4*)&Enext[n * DD + j0]     = va;
            *(float4*)&Enext[n * DD + j0 + 4] = vb;
            uint4 bv;
            bv.x = bf2pack(va.x, va.y);
            bv.y = bf2pack(va.z, va.w);
            bv.z = bf2pack(vb.x, vb.y);
            bv.w = bf2pack(vb.z, vb.w);
            *(uint4*)&Bnext[n * 32 + tx * 4] = bv;
            *(float4*)&g_alle[n * 256 + colblk + j0] =
                make_float4(va.x * inv, va.y * inv, va.z * inv, va.w * inv);
            *(float4*)&g_alle[n * 256 + colblk + j0 + 4] =
                make_float4(vb.x * inv, vb.y * inv, vb.z * inv, vb.w * inv);
        }
    }
}

// ---------------- 5: loss + fused finalize ----------------
__global__ void k_loss(const int* __restrict__ users,
                       const int* __restrict__ pos,
                       const int* __restrict__ neg,
                       float* __restrict__ out) {
    int warp = (blockIdx.x * blockDim.x + threadIdx.x) >> 5;
    int lane = threadIdx.x & 31;
    if (warp < NB) {
        int uu = users[warp];
        int pp = pos[warp];
        int nn = neg[warp];
        const float4* A4 = (const float4*)g_alle;
        float pd = 0, nd = 0, su = 0, sp = 0, sn = 0;
        #pragma unroll
        for (int t = 0; t < 2; t++) {
            float4 u = A4[uu * 64 + lane * 2 + t];
            float4 p = A4[pp * 64 + lane * 2 + t];
            float4 q = A4[nn * 64 + lane * 2 + t];
            pd += u.x * p.x + u.y * p.y + u.z * p.z + u.w * p.w;
            nd += u.x * q.x + u.y * q.y + u.z * q.z + u.w * q.w;
            su += u.x * u.x + u.y * u.y + u.z * u.z + u.w * u.w;
            sp += p.x * p.x + p.y * p.y + p.z * p.z + p.w * p.w;
            sn += q.x * q.x + q.y * q.y + q.z * q.z + q.w * q.w;
        }
        #pragma unroll
        for (int off = 16; off > 0; off >>= 1) {
            pd += __shfl_xor_sync(0xffffffffu, pd, off);
            nd += __shfl_xor_sync(0xffffffffu, nd, off);
            su += __shfl_xor_sync(0xffffffffu, su, off);
            sp += __shfl_xor_sync(0xffffffffu, sp, off);
            sn += __shfl_xor_sync(0xffffffffu, sn, off);
        }
        if (lane == 0) {
            float d = pd - nd;
            float ls = fminf(d, 0.0f) - log1pf(expf(-fabsf(d)));
            atomicAdd(&g_acc[0], ls);
            atomicAdd(&g_acc[1], su);
            atomicAdd(&g_acc[2], sp);
            atomicAdd(&g_acc[3], sn);
        }
    }
    // last-block finalize
    __threadfence();
    __syncthreads();
    if (threadIdx.x == 0) {
        int r = atomicAdd(&g_done, 1);
        if (r == LOSS_NBLK - 1) {
            float a0 = atomicAdd(&g_acc[0], 0.0f);
            float a1 = atomicAdd(&g_acc[1], 0.0f);
            float a2 = atomicAdd(&g_acc[2], 0.0f);
            float a3 = atomicAdd(&g_acc[3], 0.0f);
            float bpr = -a0 / (float)NB;
            float l2norm = (a1 + a2 + sqrtf(a3)) * 0.5f;
            out[0] = bpr + L2_REG * l2norm / (float)NB;
            g_acc[0] = 0.0f; g_acc[1] = 0.0f; g_acc[2] = 0.0f; g_acc[3] = 0.0f;
            g_done = 0;
        }
    }
}

// ---------------- launch ----------------
extern "C" void kernel_launch(void* const* d_in, const int* in_sizes, int n_in,
                              void* d_out, int out_size) {
    const int*   users = (const int*)d_in[0];
    const int*   pos   = (const int*)d_in[1];
    const int*   neg   = (const int*)d_in[2];
    const int*   rows  = (const int*)d_in[3];
    const int*   cols  = (const int*)d_in[4];
    const float* vals  = (const float*)d_in[5];
    const float* ue    = (const float*)d_in[6];
    const float* ie    = (const float*)d_in[7];
    const float* W1    = (const float*)d_in[8];
    const float* b1    = (const float*)d_in[9];
    const float* W2    = (const float*)d_in[10];
    const float* b2    = (const float*)d_in[11];
    float* out = (float*)d_out;

    cudaFuncSetAttribute(k_gemm, cudaFuncAttributeMaxDynamicSharedMemorySize,
                         GEMM_SMEM_FLOATS * sizeof(float));

    // 1: count + E init (fp32 + bf16 shadow)
    k_count_init<<<(NNZ + 255) / 256, 256>>>(rows, ue, ie);
    // 2: fused scan + scatter (in-kernel grid barrier)
    k_scan_scatter<<<SCAN_NBLK, SCAN_CHUNK>>>(rows, cols, vals);

    // layers (launch idx 5 = k_gemm L1 -> ncu capture slot)
    int cur = 0;
    for (int l = 0; l < NLAYERS; l++) {
        k_spmm<<<(NN + 7) / 8, 256>>>(cur);
        k_gemm<<<(NN + 127) / 128, 128, GEMM_SMEM_FLOATS * sizeof(float)>>>(
            cur, l, W1, b1, W2, b2);
        cur ^= 1;
    }

    // loss + fused finalize
    k_loss<<<LOSS_NBLK, 256>>>(users, pos, neg, out);
}

// round 11
// speedup vs baseline: 1.1669x; 1.0654x over previous
#include <cuda_runtime.h>
#include <math.h>
#include <stdint.h>

// Problem constants
#define NU 50000
#define NI 50000
#define NN 100000          // NU + NI
#define DD 64
#define NNZ 3200000
#define NLAYERS 3
#define NB 4096
#define L2_REG 1e-5f

#define SCAN_CHUNK 1024
#define SCAN_NBLK ((NN + SCAN_CHUNK - 1) / SCAN_CHUNK)   // 98
#define STAT_READY (1 << 30)
#define LOSS_NBLK (NB / 8)                               // 512 blocks of 8 warps

// ---------------- device scratch (no allocs allowed) ----------------
__device__ __align__(256) float g_E0[NN * DD];
__device__ __align__(256) float g_E1[NN * DD];
__device__ __align__(256) unsigned int g_B0[NN * 32];   // bf16x2 shadow of E0
__device__ __align__(256) unsigned int g_B1[NN * 32];   // bf16x2 shadow of E1
__device__ __align__(256) float g_Lmul[NN * DD];
__device__ __align__(256) float g_alle[NN * DD * (NLAYERS + 1)];   // [N, 256]
__device__ int   g_deg[NN];
__device__ int   g_rowptr[NN + 1];
__device__ int   g_cursor[NN];
__device__ __align__(16) int2 g_edge[NNZ];
__device__ int   g_stat[SCAN_NBLK];
__device__ int   g_bar;
__device__ int   g_bar2;
__device__ int   g_done;
__device__ float g_acc[4];

// ---------------- helpers ----------------
typedef unsigned long long ull;

__device__ __forceinline__ ull fma2(ull a, ull b, ull c) {
    ull d;
    asm("fma.rn.f32x2 %0, %1, %2, %3;" : "=l"(d) : "l"(a), "l"(b), "l"(c));
    return d;
}
__device__ __forceinline__ ull pk2(float lo, float hi) {
    ull d;
    asm("mov.b64 %0, {%1, %2};" : "=l"(d) : "f"(lo), "f"(hi));
    return d;
}
__device__ __forceinline__ float2 upk(ull v) {
    float2 f;
    asm("mov.b64 {%0, %1}, %2;" : "=f"(f.x), "=f"(f.y) : "l"(v));
    return f;
}
__device__ __forceinline__ unsigned int bf2pack(float lo, float hi) {
    unsigned int r;
    asm("cvt.rn.bf16x2.f32 %0, %1, %2;" : "=r"(r) : "f"(hi), "f"(lo));
    return r;
}
__device__ __forceinline__ void bfma(ull& acc, unsigned int bits, ull vv) {
    unsigned int lo = bits << 16;
    unsigned int hi = bits & 0xffff0000u;
    ull pair;
    asm("mov.b64 %0, {%1, %2};" : "=l"(pair) : "r"(lo), "r"(hi));
    acc = fma2(pair, vv, acc);
}
__device__ __forceinline__ uint32_t tf32r(float x) {
    uint32_t r;
    asm("cvt.rna.tf32.f32 %0, %1;" : "=r"(r) : "f"(x));
    return r;
}

// m16n8k8 tf32 warp MMA (baseline PTX, sm_80+; no arch-variant gating)
#define MMA_TF32(c, a, b) \
    asm volatile("mma.sync.aligned.m16n8k8.row.col.f32.tf32.tf32.f32 " \
        "{%0,%1,%2,%3}, {%4,%5,%6,%7}, {%8,%9}, {%0,%1,%2,%3};" \
        : "+f"((c)[0]), "+f"((c)[1]), "+f"((c)[2]), "+f"((c)[3]) \
        : "r"((a)[0]), "r"((a)[1]), "r"((a)[2]), "r"((a)[3]), \
          "r"((b)[0]), "r"((b)[1]))

// ---------------- 1: count + E init (fp32 + bf16 shadow) ----------------
__global__ void k_count_init(const int* __restrict__ rows,
                             const float* __restrict__ ue,
                             const float* __restrict__ ie) {
    int i = blockIdx.x * blockDim.x + threadIdx.x;
    if (i < NNZ) atomicAdd(&g_deg[rows[i]], 1);
    if (i < NN * (DD / 4)) {
        int n = i >> 4;
        int c = i & 15;
        const float4* src;
        int srow;
        if (n < NU) { src = (const float4*)ue; srow = n; }
        else        { src = (const float4*)ie; srow = n - NU; }
        float4 v = src[srow * 16 + c];
        ((float4*)g_E0)[i] = v;
        ((float4*)g_alle)[n * 64 + c] = v;
        uint2 b;
        b.x = bf2pack(v.x, v.y);
        b.y = bf2pack(v.z, v.w);
        ((uint2*)g_B0)[i] = b;
    }
}

// ---------------- 2: fused scan + scatter ----------------
__global__ void k_scan_scatter(const int* __restrict__ rows,
                               const int* __restrict__ cols,
                               const float* __restrict__ vals) {
    __shared__ int s[SCAN_CHUNK];
    __shared__ int wsum[4];
    __shared__ int s_off;
    int b = blockIdx.x;
    int t = threadIdx.x;
    int i = b * SCAN_CHUNK + t;
    int v = (i < NN) ? g_deg[i] : 0;
    if (i < NN) g_deg[i] = 0;
    s[t] = v;
    __syncthreads();
    for (int off = 1; off < SCAN_CHUNK; off <<= 1) {
        int x = 0;
        if (t >= off) x = s[t - off];
        __syncthreads();
        s[t] += x;
        __syncthreads();
    }
    if (t == SCAN_CHUNK - 1) atomicExch(&g_stat[b], s[t] | STAT_READY);
    int part = 0;
    if (t < b) {
        int st;
        do { st = atomicAdd(&g_stat[t], 0); } while (!(st & STAT_READY));
        part = st & (STAT_READY - 1);
    }
    #pragma unroll
    for (int off = 16; off > 0; off >>= 1)
        part += __shfl_xor_sync(0xffffffffu, part, off);
    if ((t & 31) == 0 && (t >> 5) < 4) wsum[t >> 5] = part;
    __syncthreads();
    if (t == 0) s_off = wsum[0] + wsum[1] + wsum[2] + wsum[3];
    __syncthreads();
    int off = s_off;
    if (i < NN) {
        int incl = s[t] + off;
        g_rowptr[1 + i] = incl;
        g_cursor[i] = incl - v;
    }
    if (b == 0 && t == 0) g_rowptr[0] = 0;

    __threadfence();
    __syncthreads();
    if (t == 0) {
        atomicAdd(&g_bar, 1);
        while (atomicAdd(&g_bar, 0) < SCAN_NBLK) { }
        g_stat[b] = 0;
        int r2 = atomicAdd(&g_bar2, 1);
        if (r2 == SCAN_NBLK - 1) { g_bar = 0; g_bar2 = 0; }
    }
    __syncthreads();

    for (int e = b * SCAN_CHUNK + t; e < NNZ; e += SCAN_NBLK * SCAN_CHUNK) {
        int r = rows[e];
        int p = atomicAdd(&g_cursor[r], 1);
        int2 pr;
        pr.x = cols[e];
        pr.y = __float_as_int(vals[e]);
        g_edge[p] = pr;
    }
}

// ---------------- 3: SpMM — warp/node, bf16 rows, 4 edges per LDG.128 ----------
__global__ void __launch_bounds__(256) k_spmm(int cur) {
    const uint4* __restrict__ B4 = (const uint4*)(cur ? g_B1 : g_B0);
    __shared__ int2 sedge[8][32];
    int warp = (blockIdx.x * blockDim.x + threadIdx.x) >> 5;
    int wid  = threadIdx.x >> 5;
    int lane = threadIdx.x & 31;
    int g    = lane >> 3;
    int sub  = lane & 7;
    if (warp >= NN) return;
    int start = g_rowptr[warp];
    int end   = g_rowptr[warp + 1];
    ull a0 = 0, a1 = 0, a2 = 0, a3 = 0;
    int e0 = start;
    for (; e0 + 32 <= end; e0 += 32) {
        sedge[wid][lane] = g_edge[e0 + lane];
        __syncwarp();
        #pragma unroll
        for (int i0 = 0; i0 < 8; i0 += 4) {
            int2 eA = sedge[wid][4 * (i0 + 0) + g];
            int2 eB = sedge[wid][4 * (i0 + 1) + g];
            int2 eC = sedge[wid][4 * (i0 + 2) + g];
            int2 eD = sedge[wid][4 * (i0 + 3) + g];
            uint4 qA = B4[eA.x * 8 + sub];
            uint4 qB = B4[eB.x * 8 + sub];
            uint4 qC = B4[eC.x * 8 + sub];
            uint4 qD = B4[eD.x * 8 + sub];
            ull vA = pk2(__int_as_float(eA.y), __int_as_float(eA.y));
            ull vB = pk2(__int_as_float(eB.y), __int_as_float(eB.y));
            ull vC = pk2(__int_as_float(eC.y), __int_as_float(eC.y));
            ull vD = pk2(__int_as_float(eD.y), __int_as_float(eD.y));
            bfma(a0, qA.x, vA); bfma(a1, qA.y, vA); bfma(a2, qA.z, vA); bfma(a3, qA.w, vA);
            bfma(a0, qB.x, vB); bfma(a1, qB.y, vB); bfma(a2, qB.z, vB); bfma(a3, qB.w, vB);
            bfma(a0, qC.x, vC); bfma(a1, qC.y, vC); bfma(a2, qC.z, vC); bfma(a3, qC.w, vC);
            bfma(a0, qD.x, vD); bfma(a1, qD.y, vD); bfma(a2, qD.z, vD); bfma(a3, qD.w, vD);
        }
        __syncwarp();
    }
    int rem = end - e0;
    if (rem > 0) {
        sedge[wid][lane] = (lane < rem) ? g_edge[e0 + lane] : make_int2(0, 0);
        __syncwarp();
        int ngrp = (rem + 3) >> 2;
        for (int i = 0; i < ngrp; i++) {
            int2 ed = sedge[wid][4 * i + g];
            uint4 q = B4[ed.x * 8 + sub];
            ull vv = pk2(__int_as_float(ed.y), __int_as_float(ed.y));
            bfma(a0, q.x, vv); bfma(a1, q.y, vv); bfma(a2, q.z, vv); bfma(a3, q.w, vv);
        }
    }
    float2 f0 = upk(a0), f1 = upk(a1), f2 = upk(a2), f3 = upk(a3);
    #pragma unroll
    for (int off = 8; off <= 16; off <<= 1) {
        f0.x += __shfl_xor_sync(0xffffffffu, f0.x, off);
        f0.y += __shfl_xor_sync(0xffffffffu, f0.y, off);
        f1.x += __shfl_xor_sync(0xffffffffu, f1.x, off);
        f1.y += __shfl_xor_sync(0xffffffffu, f1.y, off);
        f2.x += __shfl_xor_sync(0xffffffffu, f2.x, off);
        f2.y += __shfl_xor_sync(0xffffffffu, f2.y, off);
        f3.x += __shfl_xor_sync(0xffffffffu, f3.x, off);
        f3.y += __shfl_xor_sync(0xffffffffu, f3.y, off);
    }
    if (lane < 8) {
        *(float4*)&g_Lmul[warp * DD + lane * 8]     = make_float4(f0.x, f0.y, f1.x, f1.y);
        *(float4*)&g_Lmul[warp * DD + lane * 8 + 4] = make_float4(f2.x, f2.y, f3.x, f3.y);
    }
}

// ---------------- 4: GEMM via mma.sync tf32 — 128 rows/block, 4 warps -------
// Warp w: rows w*32..w*32+31 (2 m16-tiles), all 64 cols (8 n8-tiles).
// A/R/W staged in smem as tf32 bits, row pitch GP=68 (bank = 4*row+col: clean).
#define GP 68
#define OFF_AS 0
#define OFF_RS (128 * GP)
#define OFF_W1S (2 * 128 * GP)
#define OFF_W2S (2 * 128 * GP + 64 * GP)
#define OFF_BIAS (2 * 128 * GP + 2 * 64 * GP)
#define GEMM_SMEM_FLOATS (OFF_BIAS + 64)

__global__ void __launch_bounds__(128, 2) k_gemm(int cur, int l,
                                                 const float* __restrict__ W1,
                                                 const float* __restrict__ b1,
                                                 const float* __restrict__ W2,
                                                 const float* __restrict__ b2) {
    extern __shared__ float sm[];
    uint32_t* Au  = (uint32_t*)(sm + OFF_AS);    // [128][GP] tf32 bits
    uint32_t* Ru  = (uint32_t*)(sm + OFF_RS);    // [128][GP]
    uint32_t* W1u = (uint32_t*)(sm + OFF_W1S);   // [64][GP]  W'[n][k]
    uint32_t* W2u = (uint32_t*)(sm + OFF_W2S);   // [64][GP]
    float* biasS  = sm + OFF_BIAS;

    const float*  Ecur  = cur ? g_E1 : g_E0;
    float*        Enext = cur ? g_E0 : g_E1;
    unsigned int* Bnext = cur ? g_B0 : g_B1;

    int tid  = threadIdx.x;
    int wid  = tid >> 5;
    int lane = tid & 31;
    int g    = lane >> 2;        // 0..7
    int tg   = lane & 3;         // 0..3
    int rw   = wid * 32;
    int n0 = blockIdx.x * 128;
    int lw = l * 64 * 64;
    int lb = l * 64;

    if (tid < 64) biasS[tid] = b1[lb + tid] + b2[lb + tid];

    // ---- stage A = Lmul+E, R = Lmul*E (tf32-rounded), one row per thread ----
    {
        int n = n0 + tid;
        const float4* LM4 = (const float4*)g_Lmul;
        const float4* EC4 = (const float4*)Ecur;
        #pragma unroll 4
        for (int c = 0; c < 16; c++) {
            float4 lm = make_float4(0, 0, 0, 0), ev = make_float4(0, 0, 0, 0);
            if (n < NN) {
                lm = LM4[n * 16 + c];
                ev = EC4[n * 16 + c];
            }
            uint4 av, rv;
            av.x = tf32r(lm.x + ev.x); av.y = tf32r(lm.y + ev.y);
            av.z = tf32r(lm.z + ev.z); av.w = tf32r(lm.w + ev.w);
            rv.x = tf32r(lm.x * ev.x); rv.y = tf32r(lm.y * ev.y);
            rv.z = tf32r(lm.z * ev.z); rv.w = tf32r(lm.w * ev.w);
            *(uint4*)&Au[tid * GP + c * 4] = av;
            *(uint4*)&Ru[tid * GP + c * 4] = rv;
        }
    }
    // ---- stage W' (transposed: W'[n][k] = W[k][n]), tf32-rounded ----
    {
        int j  = tid >> 1;
        int kh = (tid & 1) * 32;
        #pragma unroll 8
        for (int kk = 0; kk < 32; kk++) {
            int k = kh + kk;
            W1u[j * GP + k] = tf32r(W1[lw + k * 64 + j]);
            W2u[j * GP + k] = tf32r(W2[lw + k * 64 + j]);
        }
    }
    __syncthreads();

    // ---- accumulators: c[m][jt] covers rows {rw+16m+g, +8}, cols {8jt+2tg, +1}
    float c[2][8][4];
    #pragma unroll
    for (int jt = 0; jt < 8; jt++) {
        float bv0 = biasS[8 * jt + 2 * tg];
        float bv1 = biasS[8 * jt + 2 * tg + 1];
        #pragma unroll
        for (int m = 0; m < 2; m++) {
            c[m][jt][0] = bv0; c[m][jt][1] = bv1;
            c[m][jt][2] = bv0; c[m][jt][3] = bv1;
        }
    }

    #pragma unroll 2
    for (int kb = 0; kb < 64; kb += 8) {
        uint32_t af[2][4], rf[2][4];
        #pragma unroll
        for (int m = 0; m < 2; m++) {
            int rr = rw + 16 * m + g;
            af[m][0] = Au[rr * GP + kb + tg];
            af[m][1] = Au[(rr + 8) * GP + kb + tg];
            af[m][2] = Au[rr * GP + kb + tg + 4];
            af[m][3] = Au[(rr + 8) * GP + kb + tg + 4];
            rf[m][0] = Ru[rr * GP + kb + tg];
            rf[m][1] = Ru[(rr + 8) * GP + kb + tg];
            rf[m][2] = Ru[rr * GP + kb + tg + 4];
            rf[m][3] = Ru[(rr + 8) * GP + kb + tg + 4];
        }
        #pragma unroll
        for (int jt = 0; jt < 8; jt++) {
            uint32_t w1f[2], w2f[2];
            int nn = 8 * jt + g;
            w1f[0] = W1u[nn * GP + kb + tg];
            w1f[1] = W1u[nn * GP + kb + tg + 4];
            w2f[0] = W2u[nn * GP + kb + tg];
            w2f[1] = W2u[nn * GP + kb + tg + 4];
            MMA_TF32(c[0][jt], af[0], w1f);
            MMA_TF32(c[0][jt], rf[0], w2f);
            MMA_TF32(c[1][jt], af[1], w1f);
            MMA_TF32(c[1][jt], rf[1], w2f);
        }
    }

    // ---- leaky relu + per-row sq partials ----
    // sq rows: [0]=rw+g, [1]=rw+8+g, [2]=rw+16+g, [3]=rw+24+g
    float sq[4] = {0, 0, 0, 0};
    #pragma unroll
    for (int m = 0; m < 2; m++) {
        #pragma unroll
        for (int jt = 0; jt < 8; jt++) {
            #pragma unroll
            for (int q = 0; q < 4; q++) {
                float v = c[m][jt][q];
                v = (v >= 0.0f) ? v : 0.2f * v;
                c[m][jt][q] = v;
                sq[2 * m + (q >> 1)] = fmaf(v, v, sq[2 * m + (q >> 1)]);
            }
        }
    }
    // sum across the 4 tg-lanes (same g, rows identical)
    #pragma unroll
    for (int i = 0; i < 4; i++) {
        sq[i] += __shfl_xor_sync(0xffffffffu, sq[i], 1);
        sq[i] += __shfl_xor_sync(0xffffffffu, sq[i], 2);
    }

    __syncthreads();   // all fragment LDS done -> safe to reuse As/Rs
    float* OutS = sm + OFF_AS;        // [128][GP]
    float* sqS  = sm + OFF_RS;        // [128]
    #pragma unroll
    for (int m = 0; m < 2; m++) {
        int rA = rw + 16 * m + g;
        #pragma unroll
        for (int jt = 0; jt < 8; jt++) {
            *(float2*)&OutS[rA * GP + 8 * jt + 2 * tg] =
                make_float2(c[m][jt][0], c[m][jt][1]);
            *(float2*)&OutS[(rA + 8) * GP + 8 * jt + 2 * tg] =
                make_float2(c[m][jt][2], c[m][jt][3]);
        }
    }
    if (tg == 0) {
        sqS[rw + g]      = sq[0];
        sqS[rw + 8 + g]  = sq[1];
        sqS[rw + 16 + g] = sq[2];
        sqS[rw + 24 + g] = sq[3];
    }
    __syncthreads();

    // ---- coalesced global writes ----
    {
        int tx = tid & 15;
        int ty = tid >> 4;
        int colblk = (l + 1) * 64;
        #pragma unroll 4
        for (int rr = 0; rr < 16; rr++) {
            int r = ty * 16 + rr;
            int n = n0 + r;
            if (n < NN) {
                float inv = 1.0f / fmaxf(sqrtf(sqS[r]), 1e-12f);
                const float* o = &OutS[r * GP + tx * 4];
                float4 v = make_float4(o[0], o[1], o[2], o[3]);
                *(float4*)&Enext[n * DD + tx * 4] = v;
                uint2 bv;
                bv.x = bf2pack(v.x, v.y);
                bv.y = bf2pack(v.z, v.w);
                *(uint2*)&Bnext[n * 32 + tx * 2] = bv;
                *(float4*)&g_alle[n * 256 + colblk + tx * 4] =
                    make_float4(v.x * inv, v.y * inv, v.z * inv, v.w * inv);
            }
        }
    }
}

// ---------------- 5: loss + fused finalize ----------------
__global__ void k_loss(const int* __restrict__ users,
                       const int* __restrict__ pos,
                       const int* __restrict__ neg,
                       float* __restrict__ out) {
    int warp = (blockIdx.x * blockDim.x + threadIdx.x) >> 5;
    int lane = threadIdx.x & 31;
    if (warp < NB) {
        int uu = users[warp];
        int pp = pos[warp];
        int nn = neg[warp];
        const float4* A4 = (const float4*)g_alle;
        float pd = 0, nd = 0, su = 0, sp = 0, sn = 0;
        #pragma unroll
        for (int t = 0; t < 2; t++) {
            float4 u = A4[uu * 64 + lane * 2 + t];
            float4 p = A4[pp * 64 + lane * 2 + t];
            float4 q = A4[nn * 64 + lane * 2 + t];
            pd += u.x * p.x + u.y * p.y + u.z * p.z + u.w * p.w;
            nd += u.x * q.x + u.y * q.y + u.z * q.z + u.w * q.w;
            su += u.x * u.x + u.y * u.y + u.z * u.z + u.w * u.w;
            sp += p.x * p.x + p.y * p.y + p.z * p.z + p.w * p.w;
            sn += q.x * q.x + q.y * q.y + q.z * q.z + q.w * q.w;
        }
        #pragma unroll
        for (int off = 16; off > 0; off >>= 1) {
            pd += __shfl_xor_sync(0xffffffffu, pd, off);
            nd += __shfl_xor_sync(0xffffffffu, nd, off);
            su += __shfl_xor_sync(0xffffffffu, su, off);
            sp += __shfl_xor_sync(0xffffffffu, sp, off);
            sn += __shfl_xor_sync(0xffffffffu, sn, off);
        }
        if (lane == 0) {
            float d = pd - nd;
            float ls = fminf(d, 0.0f) - log1pf(expf(-fabsf(d)));
            atomicAdd(&g_acc[0], ls);
            atomicAdd(&g_acc[1], su);
            atomicAdd(&g_acc[2], sp);
            atomicAdd(&g_acc[3], sn);
        }
    }
    __threadfence();
    __syncthreads();
    if (threadIdx.x == 0) {
        int r = atomicAdd(&g_done, 1);
        if (r == LOSS_NBLK - 1) {
            float a0 = atomicAdd(&g_acc[0], 0.0f);
            float a1 = atomicAdd(&g_acc[1], 0.0f);
            float a2 = atomicAdd(&g_acc[2], 0.0f);
            float a3 = atomicAdd(&g_acc[3], 0.0f);
            float bpr = -a0 / (float)NB;
            float l2norm = (a1 + a2 + sqrtf(a3)) * 0.5f;
            out[0] = bpr + L2_REG * l2norm / (float)NB;
            g_acc[0] = 0.0f; g_acc[1] = 0.0f; g_acc[2] = 0.0f; g_acc[3] = 0.0f;
            g_done = 0;
        }
    }
}

// ---------------- launch ----------------
extern "C" void kernel_launch(void* const* d_in, const int* in_sizes, int n_in,
                              void* d_out, int out_size) {
    const int*   users = (const int*)d_in[0];
    const int*   pos   = (const int*)d_in[1];
    const int*   neg   = (const int*)d_in[2];
    const int*   rows  = (const int*)d_in[3];
    const int*   cols  = (const int*)d_in[4];
    const float* vals  = (const float*)d_in[5];
    const float* ue    = (const float*)d_in[6];
    const float* ie    = (const float*)d_in[7];
    const float* W1    = (const float*)d_in[8];
    const float* b1    = (const float*)d_in[9];
    const float* W2    = (const float*)d_in[10];
    const float* b2    = (const float*)d_in[11];
    float* out = (float*)d_out;

    cudaFuncSetAttribute(k_gemm, cudaFuncAttributeMaxDynamicSharedMemorySize,
                         GEMM_SMEM_FLOATS * sizeof(float));

    k_count_init<<<(NNZ + 255) / 256, 256>>>(rows, ue, ie);
    k_scan_scatter<<<SCAN_NBLK, SCAN_CHUNK>>>(rows, cols, vals);

    int cur = 0;
    for (int l = 0; l < NLAYERS; l++) {
        k_spmm<<<(NN + 7) / 8, 256>>>(cur);
        k_gemm<<<(NN + 127) / 128, 128, GEMM_SMEM_FLOATS * sizeof(float)>>>(
            cur, l, W1, b1, W2, b2);
        cur ^= 1;
    }

    k_loss<<<LOSS_NBLK, 256>>>(users, pos, neg, out);
}

// round 12
// speedup vs baseline: 1.1708x; 1.0034x over previous
#include <cuda_runtime.h>
#include <math.h>
#include <stdint.h>

// Problem constants
#define NU 50000
#define NI 50000
#define NN 100000          // NU + NI
#define DD 64
#define NNZ 3200000
#define NLAYERS 3
#define NB 4096
#define L2_REG 1e-5f

#define SCAN_CHUNK 1024
#define SCAN_NBLK ((NN + SCAN_CHUNK - 1) / SCAN_CHUNK)   // 98
#define STAT_READY (1 << 30)
#define LOSS_NBLK (NB / 8)                               // 512 blocks of 8 warps

// ---------------- device scratch (no allocs allowed) ----------------
__device__ __align__(256) float g_E0[NN * DD];
__device__ __align__(256) float g_E1[NN * DD];
__device__ __align__(256) unsigned int g_B0[NN * 32];   // bf16x2 shadow of E0
__device__ __align__(256) unsigned int g_B1[NN * 32];   // bf16x2 shadow of E1
__device__ __align__(256) float g_Lmul[NN * DD];
__device__ __align__(256) float g_alle[NN * DD * (NLAYERS + 1)];   // [N, 256]
__device__ int   g_deg[NN];
__device__ int   g_rowptr[NN + 1];
__device__ int   g_cursor[NN];
__device__ __align__(16) int2 g_edge[NNZ];
__device__ int   g_stat[SCAN_NBLK];
__device__ int   g_bar;
__device__ int   g_bar2;
__device__ int   g_done;
__device__ float g_acc[4];

// ---------------- helpers ----------------
typedef unsigned long long ull;

__device__ __forceinline__ ull fma2(ull a, ull b, ull c) {
    ull d;
    asm("fma.rn.f32x2 %0, %1, %2, %3;" : "=l"(d) : "l"(a), "l"(b), "l"(c));
    return d;
}
__device__ __forceinline__ ull pk2(float lo, float hi) {
    ull d;
    asm("mov.b64 %0, {%1, %2};" : "=l"(d) : "f"(lo), "f"(hi));
    return d;
}
__device__ __forceinline__ float2 upk(ull v) {
    float2 f;
    asm("mov.b64 {%0, %1}, %2;" : "=f"(f.x), "=f"(f.y) : "l"(v));
    return f;
}
__device__ __forceinline__ unsigned int bf2pack(float lo, float hi) {
    unsigned int r;
    asm("cvt.rn.bf16x2.f32 %0, %1, %2;" : "=r"(r) : "f"(hi), "f"(lo));
    return r;
}
__device__ __forceinline__ void bfma(ull& acc, unsigned int bits, ull vv) {
    unsigned int lo = bits << 16;
    unsigned int hi = bits & 0xffff0000u;
    ull pair;
    asm("mov.b64 %0, {%1, %2};" : "=l"(pair) : "r"(lo), "r"(hi));
    acc = fma2(pair, vv, acc);
}
__device__ __forceinline__ uint32_t tf32r(float x) {
    uint32_t r;
    asm("cvt.rna.tf32.f32 %0, %1;" : "=r"(r) : "f"(x));
    return r;
}

// m16n8k8 tf32 warp MMA (baseline PTX, sm_80+; no arch-variant gating)
#define MMA_TF32(c, a, b) \
    asm volatile("mma.sync.aligned.m16n8k8.row.col.f32.tf32.tf32.f32 " \
        "{%0,%1,%2,%3}, {%4,%5,%6,%7}, {%8,%9}, {%0,%1,%2,%3};" \
        : "+f"((c)[0]), "+f"((c)[1]), "+f"((c)[2]), "+f"((c)[3]) \
        : "r"((a)[0]), "r"((a)[1]), "r"((a)[2]), "r"((a)[3]), \
          "r"((b)[0]), "r"((b)[1]))

// ---------------- 1: count + E init (fp32 + bf16 shadow) ----------------
__global__ void k_count_init(const int* __restrict__ rows,
                             const float* __restrict__ ue,
                             const float* __restrict__ ie) {
    int i = blockIdx.x * blockDim.x + threadIdx.x;
    if (i < NNZ) atomicAdd(&g_deg[rows[i]], 1);
    if (i < NN * (DD / 4)) {
        int n = i >> 4;
        int c = i & 15;
        const float4* src;
        int srow;
        if (n < NU) { src = (const float4*)ue; srow = n; }
        else        { src = (const float4*)ie; srow = n - NU; }
        float4 v = src[srow * 16 + c];
        ((float4*)g_E0)[i] = v;
        ((float4*)g_alle)[n * 64 + c] = v;
        uint2 b;
        b.x = bf2pack(v.x, v.y);
        b.y = bf2pack(v.z, v.w);
        ((uint2*)g_B0)[i] = b;
    }
}

// ---------------- 2: fused scan + scatter ----------------
__global__ void k_scan_scatter(const int* __restrict__ rows,
                               const int* __restrict__ cols,
                               const float* __restrict__ vals) {
    __shared__ int s[SCAN_CHUNK];
    __shared__ int wsum[4];
    __shared__ int s_off;
    int b = blockIdx.x;
    int t = threadIdx.x;
    int i = b * SCAN_CHUNK + t;
    int v = (i < NN) ? g_deg[i] : 0;
    if (i < NN) g_deg[i] = 0;
    s[t] = v;
    __syncthreads();
    for (int off = 1; off < SCAN_CHUNK; off <<= 1) {
        int x = 0;
        if (t >= off) x = s[t - off];
        __syncthreads();
        s[t] += x;
        __syncthreads();
    }
    if (t == SCAN_CHUNK - 1) atomicExch(&g_stat[b], s[t] | STAT_READY);
    int part = 0;
    if (t < b) {
        int st;
        do { st = atomicAdd(&g_stat[t], 0); } while (!(st & STAT_READY));
        part = st & (STAT_READY - 1);
    }
    #pragma unroll
    for (int off = 16; off > 0; off >>= 1)
        part += __shfl_xor_sync(0xffffffffu, part, off);
    if ((t & 31) == 0 && (t >> 5) < 4) wsum[t >> 5] = part;
    __syncthreads();
    if (t == 0) s_off = wsum[0] + wsum[1] + wsum[2] + wsum[3];
    __syncthreads();
    int off = s_off;
    if (i < NN) {
        int incl = s[t] + off;
        g_rowptr[1 + i] = incl;
        g_cursor[i] = incl - v;
    }
    if (b == 0 && t == 0) g_rowptr[0] = 0;

    __threadfence();
    __syncthreads();
    if (t == 0) {
        atomicAdd(&g_bar, 1);
        while (atomicAdd(&g_bar, 0) < SCAN_NBLK) { }
        g_stat[b] = 0;
        int r2 = atomicAdd(&g_bar2, 1);
        if (r2 == SCAN_NBLK - 1) { g_bar = 0; g_bar2 = 0; }
    }
    __syncthreads();

    for (int e = b * SCAN_CHUNK + t; e < NNZ; e += SCAN_NBLK * SCAN_CHUNK) {
        int r = rows[e];
        int p = atomicAdd(&g_cursor[r], 1);
        int2 pr;
        pr.x = cols[e];
        pr.y = __float_as_int(vals[e]);
        g_edge[p] = pr;
    }
}

// ---------------- 3: SpMM — warp/node, bf16 rows, 4 edges per LDG.128 ----------
__global__ void __launch_bounds__(256) k_spmm(int cur) {
    const uint4* __restrict__ B4 = (const uint4*)(cur ? g_B1 : g_B0);
    __shared__ int2 sedge[8][32];
    int warp = (blockIdx.x * blockDim.x + threadIdx.x) >> 5;
    int wid  = threadIdx.x >> 5;
    int lane = threadIdx.x & 31;
    int g    = lane >> 3;
    int sub  = lane & 7;
    if (warp >= NN) return;
    int start = g_rowptr[warp];
    int end   = g_rowptr[warp + 1];
    ull a0 = 0, a1 = 0, a2 = 0, a3 = 0;
    int e0 = start;
    for (; e0 + 32 <= end; e0 += 32) {
        sedge[wid][lane] = g_edge[e0 + lane];
        __syncwarp();
        #pragma unroll
        for (int i0 = 0; i0 < 8; i0 += 4) {
            int2 eA = sedge[wid][4 * (i0 + 0) + g];
            int2 eB = sedge[wid][4 * (i0 + 1) + g];
            int2 eC = sedge[wid][4 * (i0 + 2) + g];
            int2 eD = sedge[wid][4 * (i0 + 3) + g];
            uint4 qA = B4[eA.x * 8 + sub];
            uint4 qB = B4[eB.x * 8 + sub];
            uint4 qC = B4[eC.x * 8 + sub];
            uint4 qD = B4[eD.x * 8 + sub];
            ull vA = pk2(__int_as_float(eA.y), __int_as_float(eA.y));
            ull vB = pk2(__int_as_float(eB.y), __int_as_float(eB.y));
            ull vC = pk2(__int_as_float(eC.y), __int_as_float(eC.y));
            ull vD = pk2(__int_as_float(eD.y), __int_as_float(eD.y));
            bfma(a0, qA.x, vA); bfma(a1, qA.y, vA); bfma(a2, qA.z, vA); bfma(a3, qA.w, vA);
            bfma(a0, qB.x, vB); bfma(a1, qB.y, vB); bfma(a2, qB.z, vB); bfma(a3, qB.w, vB);
            bfma(a0, qC.x, vC); bfma(a1, qC.y, vC); bfma(a2, qC.z, vC); bfma(a3, qC.w, vC);
            bfma(a0, qD.x, vD); bfma(a1, qD.y, vD); bfma(a2, qD.z, vD); bfma(a3, qD.w, vD);
        }
        __syncwarp();
    }
    int rem = end - e0;
    if (rem > 0) {
        sedge[wid][lane] = (lane < rem) ? g_edge[e0 + lane] : make_int2(0, 0);
        __syncwarp();
        int ngrp = (rem + 3) >> 2;
        for (int i = 0; i < ngrp; i++) {
            int2 ed = sedge[wid][4 * i + g];
            uint4 q = B4[ed.x * 8 + sub];
            ull vv = pk2(__int_as_float(ed.y), __int_as_float(ed.y));
            bfma(a0, q.x, vv); bfma(a1, q.y, vv); bfma(a2, q.z, vv); bfma(a3, q.w, vv);
        }
    }
    float2 f0 = upk(a0), f1 = upk(a1), f2 = upk(a2), f3 = upk(a3);
    #pragma unroll
    for (int off = 8; off <= 16; off <<= 1) {
        f0.x += __shfl_xor_sync(0xffffffffu, f0.x, off);
        f0.y += __shfl_xor_sync(0xffffffffu, f0.y, off);
        f1.x += __shfl_xor_sync(0xffffffffu, f1.x, off);
        f1.y += __shfl_xor_sync(0xffffffffu, f1.y, off);
        f2.x += __shfl_xor_sync(0xffffffffu, f2.x, off);
        f2.y += __shfl_xor_sync(0xffffffffu, f2.y, off);
        f3.x += __shfl_xor_sync(0xffffffffu, f3.x, off);
        f3.y += __shfl_xor_sync(0xffffffffu, f3.y, off);
    }
    if (lane < 8) {
        *(float4*)&g_Lmul[warp * DD + lane * 8]     = make_float4(f0.x, f0.y, f1.x, f1.y);
        *(float4*)&g_Lmul[warp * DD + lane * 8 + 4] = make_float4(f2.x, f2.y, f3.x, f3.y);
    }
}

// ---------------- 4: GEMM via mma.sync tf32 — 128 rows/block, 8 warps ---------
// Warp w: rows w*16..w*16+15 (one m16 tile), all 64 cols (8 n8-tiles), A & R.
// Smem identical to R11 (104KB, 2 blocks/SM) but 256 threads -> 16 warps/SM.
#define GP 68
#define OFF_AS 0
#define OFF_RS (128 * GP)
#define OFF_W1S (2 * 128 * GP)
#define OFF_W2S (2 * 128 * GP + 64 * GP)
#define OFF_BIAS (2 * 128 * GP + 2 * 64 * GP)
#define GEMM_SMEM_FLOATS (OFF_BIAS + 64)

__global__ void __launch_bounds__(256, 2) k_gemm(int cur, int l,
                                                 const float* __restrict__ W1,
                                                 const float* __restrict__ b1,
                                                 const float* __restrict__ W2,
                                                 const float* __restrict__ b2) {
    extern __shared__ float sm[];
    uint32_t* Au  = (uint32_t*)(sm + OFF_AS);    // [128][GP] tf32 bits
    uint32_t* Ru  = (uint32_t*)(sm + OFF_RS);    // [128][GP]
    uint32_t* W1u = (uint32_t*)(sm + OFF_W1S);   // [64][GP]  W'[n][k]
    uint32_t* W2u = (uint32_t*)(sm + OFF_W2S);   // [64][GP]
    float* biasS  = sm + OFF_BIAS;

    const float*  Ecur  = cur ? g_E1 : g_E0;
    float*        Enext = cur ? g_E0 : g_E1;
    unsigned int* Bnext = cur ? g_B0 : g_B1;

    int tid  = threadIdx.x;
    int wid  = tid >> 5;
    int lane = tid & 31;
    int g    = lane >> 2;        // 0..7
    int tg   = lane & 3;         // 0..3
    int rw   = wid * 16;         // warp's m16 tile base row
    int n0 = blockIdx.x * 128;
    int lw = l * 64 * 64;
    int lb = l * 64;

    if (tid < 64) biasS[tid] = b1[lb + tid] + b2[lb + tid];

    // ---- stage A = Lmul+E, R = Lmul*E (tf32-rounded); half-row per thread ----
    {
        int row  = tid >> 1;
        int half = (tid & 1) * 8;
        int n = n0 + row;
        const float4* LM4 = (const float4*)g_Lmul;
        const float4* EC4 = (const float4*)Ecur;
        #pragma unroll
        for (int cc = 0; cc < 8; cc++) {
            int c = half + cc;
            float4 lm = make_float4(0, 0, 0, 0), ev = make_float4(0, 0, 0, 0);
            if (n < NN) {
                lm = LM4[n * 16 + c];
                ev = EC4[n * 16 + c];
            }
            uint4 av, rv;
            av.x = tf32r(lm.x + ev.x); av.y = tf32r(lm.y + ev.y);
            av.z = tf32r(lm.z + ev.z); av.w = tf32r(lm.w + ev.w);
            rv.x = tf32r(lm.x * ev.x); rv.y = tf32r(lm.y * ev.y);
            rv.z = tf32r(lm.z * ev.z); rv.w = tf32r(lm.w * ev.w);
            *(uint4*)&Au[row * GP + c * 4] = av;
            *(uint4*)&Ru[row * GP + c * 4] = rv;
        }
    }
    // ---- stage W' (transposed: W'[n][k] = W[k][n]), tf32-rounded ----
    {
        int j  = tid >> 2;
        int kq = (tid & 3) * 16;
        #pragma unroll
        for (int kk = 0; kk < 16; kk++) {
            int k = kq + kk;
            W1u[j * GP + k] = tf32r(W1[lw + k * 64 + j]);
            W2u[j * GP + k] = tf32r(W2[lw + k * 64 + j]);
        }
    }
    __syncthreads();

    // ---- accumulators: c[jt] covers rows {rw+g, rw+8+g}, cols {8jt+2tg, +1}
    float c[8][4];
    #pragma unroll
    for (int jt = 0; jt < 8; jt++) {
        float bv0 = biasS[8 * jt + 2 * tg];
        float bv1 = biasS[8 * jt + 2 * tg + 1];
        c[jt][0] = bv0; c[jt][1] = bv1;
        c[jt][2] = bv0; c[jt][3] = bv1;
    }

    #pragma unroll 2
    for (int kb = 0; kb < 64; kb += 8) {
        uint32_t af[4], rf[4];
        int rr = rw + g;
        af[0] = Au[rr * GP + kb + tg];
        af[1] = Au[(rr + 8) * GP + kb + tg];
        af[2] = Au[rr * GP + kb + tg + 4];
        af[3] = Au[(rr + 8) * GP + kb + tg + 4];
        rf[0] = Ru[rr * GP + kb + tg];
        rf[1] = Ru[(rr + 8) * GP + kb + tg];
        rf[2] = Ru[rr * GP + kb + tg + 4];
        rf[3] = Ru[(rr + 8) * GP + kb + tg + 4];
        #pragma unroll
        for (int jt = 0; jt < 8; jt++) {
            uint32_t w1f[2], w2f[2];
            int nn = 8 * jt + g;
            w1f[0] = W1u[nn * GP + kb + tg];
            w1f[1] = W1u[nn * GP + kb + tg + 4];
            w2f[0] = W2u[nn * GP + kb + tg];
            w2f[1] = W2u[nn * GP + kb + tg + 4];
            MMA_TF32(c[jt], af, w1f);
            MMA_TF32(c[jt], rf, w2f);
        }
    }

    // ---- leaky relu + per-row sq partials: rows rw+g (sq[0]) and rw+8+g (sq[1])
    float sq[2] = {0, 0};
    #pragma unroll
    for (int jt = 0; jt < 8; jt++) {
        #pragma unroll
        for (int q = 0; q < 4; q++) {
            float v = c[jt][q];
            v = (v >= 0.0f) ? v : 0.2f * v;
            c[jt][q] = v;
            sq[q >> 1] = fmaf(v, v, sq[q >> 1]);
        }
    }
    sq[0] += __shfl_xor_sync(0xffffffffu, sq[0], 1);
    sq[0] += __shfl_xor_sync(0xffffffffu, sq[0], 2);
    sq[1] += __shfl_xor_sync(0xffffffffu, sq[1], 1);
    sq[1] += __shfl_xor_sync(0xffffffffu, sq[1], 2);

    __syncthreads();   // all fragment LDS done -> safe to reuse As/Rs
    float* OutS = sm + OFF_AS;        // [128][GP]
    float* sqS  = sm + OFF_RS;        // [128]
    {
        int rA = rw + g;
        #pragma unroll
        for (int jt = 0; jt < 8; jt++) {
            *(float2*)&OutS[rA * GP + 8 * jt + 2 * tg] =
                make_float2(c[jt][0], c[jt][1]);
            *(float2*)&OutS[(rA + 8) * GP + 8 * jt + 2 * tg] =
                make_float2(c[jt][2], c[jt][3]);
        }
        if (tg == 0) {
            sqS[rA]     = sq[0];
            sqS[rA + 8] = sq[1];
        }
    }
    __syncthreads();

    // ---- coalesced global writes (256 threads: 8 rows each group) ----
    {
        int tx = tid & 15;
        int ty = tid >> 4;           // 0..15
        int colblk = (l + 1) * 64;
        #pragma unroll 4
        for (int rr = 0; rr < 8; rr++) {
            int r = ty * 8 + rr;
            int n = n0 + r;
            if (n < NN) {
                float inv = 1.0f / fmaxf(sqrtf(sqS[r]), 1e-12f);
                const float* o = &OutS[r * GP + tx * 4];
                float4 v = make_float4(o[0], o[1], o[2], o[3]);
                *(float4*)&Enext[n * DD + tx * 4] = v;
                uint2 bv;
                bv.x = bf2pack(v.x, v.y);
                bv.y = bf2pack(v.z, v.w);
                *(uint2*)&Bnext[n * 32 + tx * 2] = bv;
                *(float4*)&g_alle[n * 256 + colblk + tx * 4] =
                    make_float4(v.x * inv, v.y * inv, v.z * inv, v.w * inv);
            }
        }
    }
}

// ---------------- 5: loss + fused finalize ----------------
__global__ void k_loss(const int* __restrict__ users,
                       const int* __restrict__ pos,
                       const int* __restrict__ neg,
                       float* __restrict__ out) {
    int warp = (blockIdx.x * blockDim.x + threadIdx.x) >> 5;
    int lane = threadIdx.x & 31;
    if (warp < NB) {
        int uu = users[warp];
        int pp = pos[warp];
        int nn = neg[warp];
        const float4* A4 = (const float4*)g_alle;
        float pd = 0, nd = 0, su = 0, sp = 0, sn = 0;
        #pragma unroll
        for (int t = 0; t < 2; t++) {
            float4 u = A4[uu * 64 + lane * 2 + t];
            float4 p = A4[pp * 64 + lane * 2 + t];
            float4 q = A4[nn * 64 + lane * 2 + t];
            pd += u.x * p.x + u.y * p.y + u.z * p.z + u.w * p.w;
            nd += u.x * q.x + u.y * q.y + u.z * q.z + u.w * q.w;
            su += u.x * u.x + u.y * u.y + u.z * u.z + u.w * u.w;
            sp += p.x * p.x + p.y * p.y + p.z * p.z + p.w * p.w;
            sn += q.x * q.x + q.y * q.y + q.z * q.z + q.w * q.w;
        }
        #pragma unroll
        for (int off = 16; off > 0; off >>= 1) {
            pd += __shfl_xor_sync(0xffffffffu, pd, off);
            nd += __shfl_xor_sync(0xffffffffu, nd, off);
            su += __shfl_xor_sync(0xffffffffu, su, off);
            sp += __shfl_xor_sync(0xffffffffu, sp, off);
            sn += __shfl_xor_sync(0xffffffffu, sn, off);
        }
        if (lane == 0) {
            float d = pd - nd;
            float ls = fminf(d, 0.0f) - log1pf(expf(-fabsf(d)));
            atomicAdd(&g_acc[0], ls);
            atomicAdd(&g_acc[1], su);
            atomicAdd(&g_acc[2], sp);
            atomicAdd(&g_acc[3], sn);
        }
    }
    __threadfence();
    __syncthreads();
    if (threadIdx.x == 0) {
        int r = atomicAdd(&g_done, 1);
        if (r == LOSS_NBLK - 1) {
            float a0 = atomicAdd(&g_acc[0], 0.0f);
            float a1 = atomicAdd(&g_acc[1], 0.0f);
            float a2 = atomicAdd(&g_acc[2], 0.0f);
            float a3 = atomicAdd(&g_acc[3], 0.0f);
            float bpr = -a0 / (float)NB;
            float l2norm = (a1 + a2 + sqrtf(a3)) * 0.5f;
            out[0] = bpr + L2_REG * l2norm / (float)NB;
            g_acc[0] = 0.0f; g_acc[1] = 0.0f; g_acc[2] = 0.0f; g_acc[3] = 0.0f;
            g_done = 0;
        }
    }
}

// ---------------- launch ----------------
extern "C" void kernel_launch(void* const* d_in, const int* in_sizes, int n_in,
                              void* d_out, int out_size) {
    const int*   users = (const int*)d_in[0];
    const int*   pos   = (const int*)d_in[1];
    const int*   neg   = (const int*)d_in[2];
    const int*   rows  = (const int*)d_in[3];
    const int*   cols  = (const int*)d_in[4];
    const float* vals  = (const float*)d_in[5];
    const float* ue    = (const float*)d_in[6];
    const float* ie    = (const float*)d_in[7];
    const float* W1    = (const float*)d_in[8];
    const float* b1    = (const float*)d_in[9];
    const float* W2    = (const float*)d_in[10];
    const float* b2    = (const float*)d_in[11];
    float* out = (float*)d_out;

    cudaFuncSetAttribute(k_gemm, cudaFuncAttributeMaxDynamicSharedMemorySize,
                         GEMM_SMEM_FLOATS * sizeof(float));

    k_count_init<<<(NNZ + 255) / 256, 256>>>(rows, ue, ie);
    k_scan_scatter<<<SCAN_NBLK, SCAN_CHUNK>>>(rows, cols, vals);

    int cur = 0;
    for (int l = 0; l < NLAYERS; l++) {
        k_spmm<<<(NN + 7) / 8, 256>>>(cur);
        k_gemm<<<(NN + 127) / 128, 256, GEMM_SMEM_FLOATS * sizeof(float)>>>(
            cur, l, W1, b1, W2, b2);
        cur ^= 1;
    }

    k_loss<<<LOSS_NBLK, 256>>>(users, pos, neg, out);
}